// round 14
// baseline (speedup 1.0000x reference)
#include <cuda_runtime.h>
#include <cuda_fp16.h>
#include <math.h>

// Problem constants
#define B_      256
#define U_      512
#define T_STEPS 256
#define NTn     8       // n tiles (512 / 64)
#define N_TILE  64
#define NCOMP   128     // compute CTAs (16 m-groups x 8 n-tiles)
#define NRED    8       // reducer CTAs
#define THREADS 256
#define WT_STRIDE 1032  // padded row stride (halfs): conflict-free LDSM
#define ZDEPTH  8

// Packed hidden-state storage: slab(par,col) = [m=16][kk=32][j=4][lane=32] u32
__device__ unsigned int g_statesP[2 * 16 * 16 * 32 * 4 * 32];
// logit partials: [ZDEPTH][NTn][4 warps][B] float2
__device__ float2 g_zpart[ZDEPTH * NTn * 4 * B_];

// padded sync cells: one 128B line each (no line sharing between groups)
struct PadCnt { int v; int pad[31]; };
__device__ PadCnt g_scnt[16];   // state counters: +8 per m-group per step
__device__ PadCnt g_zcnt[16];   // z counters: +8 per m-group per step
__device__ PadCnt g_rfl[8];     // reducer progress

__device__ __forceinline__ int ld_acquire(const int* p) {
    int v;
    asm volatile("ld.global.acquire.gpu.b32 %0, [%1];" : "=r"(v) : "l"(p) : "memory");
    return v;
}
__device__ __forceinline__ void st_release(int* p, int v) {
    asm volatile("st.global.release.gpu.b32 [%0], %1;" :: "l"(p), "r"(v) : "memory");
}
__device__ __forceinline__ void red_release_add(int* p, int v) {
    asm volatile("red.release.gpu.global.add.s32 [%0], %1;" :: "l"(p), "r"(v) : "memory");
}
__device__ __forceinline__ float2 ldg_cg_f2(const float2* p) {
    float2 v;
    asm volatile("ld.global.cg.v2.f32 {%0,%1}, [%2];" : "=f"(v.x), "=f"(v.y) : "l"(p));
    return v;
}
__device__ __forceinline__ void cp_async16(unsigned smem_addr, const void* gptr) {
    asm volatile("cp.async.cg.shared.global [%0], [%1], 16;"
                 :: "r"(smem_addr), "l"(gptr));
}
__device__ __forceinline__ void cp_commit() {
    asm volatile("cp.async.commit_group;");
}
template <int N>
__device__ __forceinline__ void cp_wait() {
    asm volatile("cp.async.wait_group %0;" :: "n"(N) : "memory");
}
__device__ __forceinline__ void bar_sync(int id, int cnt) {
    asm volatile("bar.sync %0, %1;" :: "r"(id), "r"(cnt) : "memory");
}

__device__ __forceinline__ void mma16816(float acc[4],
    unsigned a0, unsigned a1, unsigned a2, unsigned a3,
    unsigned b0, unsigned b1)
{
    asm volatile(
        "mma.sync.aligned.m16n8k16.row.col.f32.f16.f16.f32 "
        "{%0,%1,%2,%3}, {%4,%5,%6,%7}, {%8,%9}, {%0,%1,%2,%3};"
        : "+f"(acc[0]), "+f"(acc[1]), "+f"(acc[2]), "+f"(acc[3])
        : "r"(a0), "r"(a1), "r"(a2), "r"(a3), "r"(b0), "r"(b1));
}

__device__ __forceinline__ unsigned* pslab(int par, int col) {
    return g_statesP + (((par << 4) + col) << 16);   // 65536 u32 per slab
}

// KKN-step half-GEMM via ldmatrix.x4 (A packed [kk][j][lane], B = weight slice)
template <int KKN>
__device__ __forceinline__ void gemm_ldsm_n(unsigned aB, unsigned bB, float acc[2][4]) {
#pragma unroll 8
    for (int kk = 0; kk < KKN; ++kk) {
        unsigned a0, a1, a2, a3, b0, b1, b2, b3;
        asm volatile("ldmatrix.sync.aligned.m8n8.x4.shared.b16 {%0,%1,%2,%3}, [%4];"
            : "=r"(a0), "=r"(a1), "=r"(a2), "=r"(a3) : "r"(aB));
        asm volatile("ldmatrix.sync.aligned.m8n8.x4.shared.b16 {%0,%1,%2,%3}, [%4];"
            : "=r"(b0), "=r"(b1), "=r"(b2), "=r"(b3) : "r"(bB));
        mma16816(acc[0], a0, a1, a2, a3, b0, b1);
        mma16816(acc[1], a0, a1, a2, a3, b2, b3);
        aB += 512;
        bB += 32;
    }
}

__device__ __forceinline__ float elu1(float v) {
    return v > 0.f ? v : (__expf(v) - 1.f);
}
__device__ __forceinline__ unsigned packh2(float a, float b) {
    __half2 h = __floats2half2_rn(a, b);
    return *reinterpret_cast<unsigned*>(&h);
}

// ---- smem layout offsets (bytes) ----
#define SM_WT    0                       // 64 x 1032 halves = 132096
#define SM_CV    132096                  // cv stage, 16 KB
#define SM_FR    148480                  // fresh stage, 16 KB
#define SM_PART  164864                  // cv fp32 partials, double buffered, 8 KB
#define SM_SMALL 173056                  // 448 floats = 1792
#define SM_SX    174848                  // 8192 (reducers cache 32 rows)
#define SM_TOTAL 183040

__global__ void rnn2d_init_kernel() {
    if (threadIdx.x < 16) { g_scnt[threadIdx.x].v = 0; g_zcnt[threadIdx.x].v = 0; }
    if (threadIdx.x < NRED) g_rfl[threadIdx.x].v = 0;
}

__global__ void __launch_bounds__(THREADS) rnn2d_main_kernel(
    const int* __restrict__ x,
    const float* __restrict__ Wih, const float* __restrict__ Wiv,
    const float* __restrict__ Wch, const float* __restrict__ bch,
    const float* __restrict__ Wcv, const float* __restrict__ Wout,
    const float* __restrict__ bout, float* __restrict__ out)
{
    extern __shared__ unsigned char smem[];
    __half* Wt   = (__half*)(smem + SM_WT);
    float*  sPart= (float*)(smem + SM_PART);     // [2 par][4 warps][32 lanes][8]
    float* sWih  = (float*)(smem + SM_SMALL);
    float* sWiv  = sWih + 128;
    float* sBch  = sWiv + 128;
    float* sWo0  = sBch + 64;
    float* sWo1  = sWo0 + 64;
    unsigned char* sx = (unsigned char*)(smem + SM_SX);

    const int bx  = blockIdx.x;
    const int tid = threadIdx.x;

    if (bx >= NCOMP) {
        // ---------------- reducer CTA (off the critical path) ----------------
        const int mr = bx - NCOMP;                 // rows 32*mr .. 32*mr+31
        for (int i = tid; i < 8192; i += THREADS) {
            int rl = i & 31, cell = i >> 5;
            sx[cell * 32 + rl] = (unsigned char)x[(32 * mr + rl) * 256 + cell];
        }
        __syncthreads();
        if (tid >= 32) return;

        const int lane = tid;
        const int b = 32 * mr + lane;
        const float bo0 = bout[0], bo1 = bout[1];
        float lp = 0.f;
        for (int t = 1; t <= T_STEPS; ++t) {
            if (lane < 2) {                        // one z-counter per m-group
                while (ld_acquire(&g_zcnt[2 * mr + lane].v) < 8 * t) { }
            }
            __syncwarp();
            asm volatile("membar.gl;" ::: "memory");
            float z0 = bo0, z1 = bo1;
            const float2* zp = g_zpart + (t & (ZDEPTH - 1)) * (NTn * 4 * B_) + b;
#pragma unroll
            for (int i = 0; i < 32; ++i) {
                float2 v = ldg_cg_f2(zp + i * B_);
                z0 += v.x; z1 += v.y;
            }
            int s = t - 1, r = s >> 4, p = s & 15;
            int c = (r & 1) ? (15 - p) : p;
            int spin = sx[(r * 16 + c) * 32 + lane];
            float mz = fmaxf(z0, z1);
            float lse = mz + logf(expf(z0 - mz) + expf(z1 - mz));
            lp += (spin ? z1 : z0) - lse;
            __syncwarp();
            if (lane == 0) st_release(&g_rfl[mr].v, t);
        }
        out[b] = lp;
        return;
    }

    // ---------------- compute CTA ----------------
    const int m = bx >> 3, n = bx & 7;           // 16-row group, 64-col tile
    const int w = tid >> 5, lane = tid & 31;
    const int wc = w & 3;                        // column group (16 cols)
    const bool isF = (w < 4);                    // fresh group vs cv group
    const int n0 = n * N_TILE;
    const int q = lane >> 2, tg = lane & 3;

    const unsigned sCV_s = (unsigned)__cvta_generic_to_shared(smem + SM_CV);
    const unsigned sFR_s = (unsigned)__cvta_generic_to_shared(smem + SM_FR);
    const unsigned wt_s  = (unsigned)__cvta_generic_to_shared(Wt);
    const unsigned aOff  = ((lane >> 3) << 7) + ((lane & 7) << 4);
    const unsigned brow  = 16 * wc + 8 * (lane >> 4) + (lane & 7);
    const unsigned bOff  = wt_s + brow * (WT_STRIDE * 2) + (((lane >> 3) & 1) << 4);

    // resident weight slice: Wt[j][k] = W[k][n0+j]
    for (int i = tid; i < N_TILE * 1024; i += THREADS) {
        int j = i >> 10, k = i & 1023;
        float wv = (k < U_) ? Wch[k * U_ + n0 + j] : Wcv[(k - U_) * U_ + n0 + j];
        Wt[j * WT_STRIDE + k] = __float2half_rn(wv);
    }
    if (tid < 64) {
        sWih[tid]       = Wih[n0 + tid];
        sWih[64 + tid]  = Wih[U_ + n0 + tid];
        sWiv[tid]       = Wiv[n0 + tid];
        sWiv[64 + tid]  = Wiv[U_ + n0 + tid];
        sBch[tid]       = bch[n0 + tid];
        sWo0[tid]       = Wout[(n0 + tid) * 2 + 0];
        sWo1[tid]       = Wout[(n0 + tid) * 2 + 1];
    }
    for (int i = tid; i < 4096; i += THREADS) {  // spins for this CTA's 16 rows
        int rl = i & 15, cell = i >> 4;
        sx[cell * 16 + rl] = (unsigned char)x[(16 * m + rl) * 256 + cell];
    }
    __syncthreads();

#pragma unroll 1
    for (int t = 1; t <= T_STEPS; ++t) {
        const int s = t - 1;
        const int r = s >> 4, p = s & 15;
        const int c  = (r & 1) ? (15 - p) : p;
        const int cp = (r & 1) ? (c + 1) : (c - 1);
        const bool has_h = (p > 0), has_v = (r > 0);
        const bool oldcv = has_h && has_v;       // old-cv GEMM active this step
        float* sP = sPart + (t & 1) * 1024;      // parity-selected partial buffer

        if (isF) {
            // ======== FRESH GROUP (warps 0-3, tid 0..127) ========
            if (w == 0 && t > 1) {
                if (lane == 0) {                 // single aggregated counter poll
                    while (ld_acquire(&g_scnt[m].v) < 8 * (t - 1)) { }
                }
                if (lane == 1 && t > ZDEPTH) {   // z-ring back-pressure
                    while (ld_acquire(&g_rfl[m >> 1].v) < t - ZDEPTH) { }
                }
            }
            bar_sync(1, 128);                    // deps acquired (fresh group)

            float acc[2][4];
#pragma unroll
            for (int f = 0; f < 2; ++f)
                acc[f][0] = acc[f][1] = acc[f][2] = acc[f][3] = 0.f;

            if (t > 1) {
                const unsigned* fsrc = has_h ? (pslab(r & 1, cp) + (m << 12))
                                             : (pslab((r - 1) & 1, c) + (m << 12));
                // two 8KB chunks -> copy/GEMM overlap
#pragma unroll
                for (int i = 0; i < 4; ++i)
                    cp_async16(sFR_s + tid * 16 + i * 2048, fsrc + tid * 4 + i * 512);
                cp_commit();
#pragma unroll
                for (int i = 4; i < 8; ++i)
                    cp_async16(sFR_s + tid * 16 + i * 2048, fsrc + tid * 4 + i * 512);
                cp_commit();

                const unsigned bB = has_h ? bOff : bOff + 1024;
                cp_wait<1>();
                bar_sync(1, 128);                // first half staged
                gemm_ldsm_n<16>(sFR_s + aOff, bB, acc);
                cp_wait<0>();
                bar_sync(1, 128);                // second half staged
                gemm_ldsm_n<16>(sFR_s + 8192 + aOff, bB + 512, acc);
            }

            __syncthreads();                     // join: cv partials in sPart[par]

            if (oldcv) {
                const float4* pp = (const float4*)(sP + (wc * 32 + lane) * 8);
                float4 pa = pp[0], pb = pp[1];
                acc[0][0] += pa.x; acc[0][1] += pa.y; acc[0][2] += pa.z; acc[0][3] += pa.w;
                acc[1][0] += pb.x; acc[1][1] += pb.y; acc[1][2] += pb.z; acc[1][3] += pb.w;
            }

            // ---- epilogue
            int sLa = 0, sLb = 0, sUa = 0, sUb = 0;
            if (has_h) {
                sLa = sx[(r * 16 + cp) * 16 + q];
                sLb = sx[(r * 16 + cp) * 16 + q + 8];
            }
            if (has_v) {
                sUa = sx[((r - 1) * 16 + c) * 16 + q];
                sUb = sx[((r - 1) * 16 + c) * 16 + q + 8];
            }

            float z0a = 0.f, z1a = 0.f, z0b = 0.f, z1b = 0.f;
            unsigned* Pout = pslab(r & 1, c) + (m << 12) + ((4 * n + w) << 7) + lane;
#pragma unroll
            for (int f = 0; f < 2; ++f) {
                int u0 = 16 * w + 8 * f + 2 * tg;
                float v0 = acc[f][0] + sBch[u0];
                float v1 = acc[f][1] + sBch[u0 + 1];
                float v2 = acc[f][2] + sBch[u0];
                float v3 = acc[f][3] + sBch[u0 + 1];
                if (has_h) {
                    v0 += sWih[sLa * 64 + u0]; v1 += sWih[sLa * 64 + u0 + 1];
                    v2 += sWih[sLb * 64 + u0]; v3 += sWih[sLb * 64 + u0 + 1];
                }
                if (has_v) {
                    v0 += sWiv[sUa * 64 + u0]; v1 += sWiv[sUa * 64 + u0 + 1];
                    v2 += sWiv[sUb * 64 + u0]; v3 += sWiv[sUb * 64 + u0 + 1];
                }
                v0 = elu1(v0); v1 = elu1(v1); v2 = elu1(v2); v3 = elu1(v3);

                z0a += v0 * sWo0[u0] + v1 * sWo0[u0 + 1];
                z1a += v0 * sWo1[u0] + v1 * sWo1[u0 + 1];
                z0b += v2 * sWo0[u0] + v3 * sWo0[u0 + 1];
                z1b += v2 * sWo1[u0] + v3 * sWo1[u0 + 1];

                Pout[(2 * f) * 32]     = packh2(v0, v1);
                Pout[(2 * f + 1) * 32] = packh2(v2, v3);
            }

            // EARLY release: peers only need the Pout stores
            bar_sync(1, 128);
            if (tid == 0) red_release_add(&g_scnt[m].v, 1);

            // ---- z tail (reducer consumers only) — off the peer-critical path
            z0a += __shfl_xor_sync(0xffffffffu, z0a, 1);
            z0a += __shfl_xor_sync(0xffffffffu, z0a, 2);
            z1a += __shfl_xor_sync(0xffffffffu, z1a, 1);
            z1a += __shfl_xor_sync(0xffffffffu, z1a, 2);
            z0b += __shfl_xor_sync(0xffffffffu, z0b, 1);
            z0b += __shfl_xor_sync(0xffffffffu, z0b, 2);
            z1b += __shfl_xor_sync(0xffffffffu, z1b, 1);
            z1b += __shfl_xor_sync(0xffffffffu, z1b, 2);
            if (tg == 0) {
                float2* zp = g_zpart + (((t & (ZDEPTH - 1)) * NTn + n) * 4 + w) * B_;
                int bA = 16 * m + q;
                zp[bA]     = make_float2(z0a, z1a);
                zp[bA + 8] = make_float2(z0b, z1b);
            }
            bar_sync(1, 128);
            if (tid == 0) red_release_add(&g_zcnt[m].v, 1);
        } else {
            // ======== CV GROUP (warps 4-7, tid 128..255) ========
            if (oldcv) {
                cp_wait<0>();                    // own prefetch (end of t-1) landed
                bar_sync(2, 128);                // whole cv group staged
                float acc[2][4];
#pragma unroll
                for (int f = 0; f < 2; ++f)
                    acc[f][0] = acc[f][1] = acc[f][2] = acc[f][3] = 0.f;
                gemm_ldsm_n<32>(sCV_s + aOff, bOff + 1024, acc);
                float4* pp = (float4*)(sP + (wc * 32 + lane) * 8);
                pp[0] = make_float4(acc[0][0], acc[0][1], acc[0][2], acc[0][3]);
                pp[1] = make_float4(acc[1][0], acc[1][1], acc[1][2], acc[1][3]);
            }
            bar_sync(2, 128);                    // cv group done reading sCV

            // prefetch next step's old-cv tile into sCV
            if (t < T_STEPS) {
                int r2 = t >> 4, p2 = t & 15;
                if (p2 >= 1 && r2 >= 1) {
                    int c2 = (r2 & 1) ? (15 - p2) : p2;
                    const unsigned* src = pslab((r2 - 1) & 1, c2) + (m << 12);
                    int tl = tid - 128;
#pragma unroll
                    for (int i = 0; i < 8; ++i)
                        cp_async16(sCV_s + tl * 16 + i * 2048, src + tl * 4 + i * 512);
                }
                cp_commit();
            }

            __syncthreads();                     // join (partials visible to fresh)
        }
    }
}

extern "C" void kernel_launch(void* const* d_in, const int* in_sizes, int n_in,
                              void* d_out, int out_size)
{
    (void)in_sizes; (void)n_in; (void)out_size;
    const int*   x    = (const int*)  d_in[0];
    const float* Wih  = (const float*)d_in[1];
    const float* Wiv  = (const float*)d_in[2];
    const float* Wch  = (const float*)d_in[3];
    const float* bch  = (const float*)d_in[4];
    const float* Wcv  = (const float*)d_in[5];
    const float* Wout = (const float*)d_in[6];
    const float* bout = (const float*)d_in[7];
    float* out = (float*)d_out;

    cudaFuncSetAttribute(rnn2d_main_kernel,
                         cudaFuncAttributeMaxDynamicSharedMemorySize, SM_TOTAL);

    rnn2d_init_kernel<<<1, 128>>>();
    rnn2d_main_kernel<<<NCOMP + NRED, THREADS, SM_TOTAL>>>(
        x, Wih, Wiv, Wch, bch, Wcv, Wout, bout, out);
}

// round 15
// speedup vs baseline: 1.2261x; 1.2261x over previous
#include <cuda_runtime.h>
#include <cuda_fp16.h>
#include <math.h>

// Problem constants
#define B_      256
#define U_      512
#define T_STEPS 256
#define NTn     8       // n tiles (512 / 64)
#define N_TILE  64
#define NCOMP   128     // compute CTAs (16 m-groups x 8 n-tiles)
#define NRED    8       // reducer CTAs
#define THREADS 256
#define WT_STRIDE 1032  // padded row stride (halfs): conflict-free LDSM
#define ZDEPTH  8

// Packed hidden-state storage: slab(par,col) = [m=16][kk=32][j=4][lane=32] u32
__device__ unsigned int g_statesP[2 * 16 * 16 * 32 * 4 * 32];
// logit partials: [ZDEPTH][NTn][4 warps][B] float2
__device__ float2 g_zpart[ZDEPTH * NTn * 4 * B_];
// per-CTA completed-step counters (8 per m-group), reducer flags
__device__ int g_flags[NCOMP];
__device__ int g_rflags[NRED];

// ---- smem layout offsets (bytes) ----
#define SM_WT    0                       // 64 x 1032 halves = 132096
#define SM_CV    132096                  // cv stage, 16 KB
#define SM_FR    148480                  // fresh stage, 16 KB
#define SM_PART  164864                  // cv fp32 partials, double buffered, 8 KB
#define SM_SMALL 173056                  // 448 floats = 1792
#define SM_SX    174848                  // 8192 (reducers cache 32 rows)
#define SM_TOTAL 183040

__device__ __forceinline__ int ld_acquire(const int* p) {
    int v;
    asm volatile("ld.global.acquire.gpu.b32 %0, [%1];" : "=r"(v) : "l"(p) : "memory");
    return v;
}
__device__ __forceinline__ void st_release(int* p, int v) {
    asm volatile("st.global.release.gpu.b32 [%0], %1;" :: "l"(p), "r"(v) : "memory");
}
__device__ __forceinline__ float2 ldg_cg_f2(const float2* p) {
    float2 v;
    asm volatile("ld.global.cg.v2.f32 {%0,%1}, [%2];" : "=f"(v.x), "=f"(v.y) : "l"(p));
    return v;
}
__device__ __forceinline__ void cp_async16(unsigned smem_addr, const void* gptr) {
    asm volatile("cp.async.cg.shared.global [%0], [%1], 16;"
                 :: "r"(smem_addr), "l"(gptr));
}
__device__ __forceinline__ void cp_commit() {
    asm volatile("cp.async.commit_group;");
}
template <int N>
__device__ __forceinline__ void cp_wait() {
    asm volatile("cp.async.wait_group %0;" :: "n"(N) : "memory");
}
__device__ __forceinline__ void bar_sync(int id, int cnt) {
    asm volatile("bar.sync %0, %1;" :: "r"(id), "r"(cnt) : "memory");
}

__device__ __forceinline__ void mma16816(float acc[4],
    unsigned a0, unsigned a1, unsigned a2, unsigned a3,
    unsigned b0, unsigned b1)
{
    asm volatile(
        "mma.sync.aligned.m16n8k16.row.col.f32.f16.f16.f32 "
        "{%0,%1,%2,%3}, {%4,%5,%6,%7}, {%8,%9}, {%0,%1,%2,%3};"
        : "+f"(acc[0]), "+f"(acc[1]), "+f"(acc[2]), "+f"(acc[3])
        : "r"(a0), "r"(a1), "r"(a2), "r"(a3), "r"(b0), "r"(b1));
}

__device__ __forceinline__ unsigned* pslab(int par, int col) {
    return g_statesP + (((par << 4) + col) << 16);   // 65536 u32 per slab
}

// KKN-step half-GEMM via ldmatrix.x4 (A packed [kk][j][lane], B = weight slice)
template <int KKN>
__device__ __forceinline__ void gemm_ldsm_n(unsigned aB, unsigned bB, float acc[2][4]) {
#pragma unroll 8
    for (int kk = 0; kk < KKN; ++kk) {
        unsigned a0, a1, a2, a3, b0, b1, b2, b3;
        asm volatile("ldmatrix.sync.aligned.m8n8.x4.shared.b16 {%0,%1,%2,%3}, [%4];"
            : "=r"(a0), "=r"(a1), "=r"(a2), "=r"(a3) : "r"(aB));
        asm volatile("ldmatrix.sync.aligned.m8n8.x4.shared.b16 {%0,%1,%2,%3}, [%4];"
            : "=r"(b0), "=r"(b1), "=r"(b2), "=r"(b3) : "r"(bB));
        mma16816(acc[0], a0, a1, a2, a3, b0, b1);
        mma16816(acc[1], a0, a1, a2, a3, b2, b3);
        aB += 512;
        bB += 32;
    }
}

__device__ __forceinline__ float elu1(float v) {
    return v > 0.f ? v : (__expf(v) - 1.f);
}
__device__ __forceinline__ unsigned packh2(float a, float b) {
    __half2 h = __floats2half2_rn(a, b);
    return *reinterpret_cast<unsigned*>(&h);
}

__global__ void rnn2d_init_kernel() {
    if (threadIdx.x < NCOMP) g_flags[threadIdx.x] = 0;
    if (threadIdx.x < NRED)  g_rflags[threadIdx.x] = 0;
}

__global__ void __launch_bounds__(THREADS) rnn2d_main_kernel(
    const int* __restrict__ x,
    const float* __restrict__ Wih, const float* __restrict__ Wiv,
    const float* __restrict__ Wch, const float* __restrict__ bch,
    const float* __restrict__ Wcv, const float* __restrict__ Wout,
    const float* __restrict__ bout, float* __restrict__ out)
{
    extern __shared__ unsigned char smem[];
    __half* Wt   = (__half*)(smem + SM_WT);
    float*  sPart= (float*)(smem + SM_PART);     // [2 par][4 warps][32 lanes][8]
    float* sWih  = (float*)(smem + SM_SMALL);
    float* sWiv  = sWih + 128;
    float* sBch  = sWiv + 128;
    float* sWo0  = sBch + 64;
    float* sWo1  = sWo0 + 64;
    unsigned char* sx = (unsigned char*)(smem + SM_SX);

    const int bx  = blockIdx.x;
    const int tid = threadIdx.x;

    if (bx >= NCOMP) {
        // ---------------- reducer CTA (off the critical path) ----------------
        const int mr = bx - NCOMP;                 // rows 32*mr .. 32*mr+31
        for (int i = tid; i < 8192; i += THREADS) {
            int rl = i & 31, cell = i >> 5;
            sx[cell * 32 + rl] = (unsigned char)x[(32 * mr + rl) * 256 + cell];
        }
        __syncthreads();
        if (tid >= 32) return;

        const int lane = tid;
        const int b = 32 * mr + lane;
        const float bo0 = bout[0], bo1 = bout[1];
        int* myflags = g_flags + 16 * mr;          // 2 m-groups x 8 flags
        float lp = 0.f;
        for (int t = 1; t <= T_STEPS; ++t) {
            if (lane < 16) {
                while (ld_acquire(myflags + lane) < t) { }
            }
            __syncwarp();
            asm volatile("membar.gl;" ::: "memory");
            float z0 = bo0, z1 = bo1;
            const float2* zp = g_zpart + (t & (ZDEPTH - 1)) * (NTn * 4 * B_) + b;
#pragma unroll
            for (int i = 0; i < 32; ++i) {
                float2 v = ldg_cg_f2(zp + i * B_);
                z0 += v.x; z1 += v.y;
            }
            int s = t - 1, r = s >> 4, p = s & 15;
            int c = (r & 1) ? (15 - p) : p;
            int spin = sx[(r * 16 + c) * 32 + lane];
            float mz = fmaxf(z0, z1);
            float lse = mz + logf(expf(z0 - mz) + expf(z1 - mz));
            lp += (spin ? z1 : z0) - lse;
            __syncwarp();
            if (lane == 0) st_release(&g_rflags[mr], t);
        }
        out[b] = lp;
        return;
    }

    // ---------------- compute CTA ----------------
    const int m = bx >> 3, n = bx & 7;           // 16-row group, 64-col tile
    const int w = tid >> 5, lane = tid & 31;
    const int wc = w & 3;                        // column group (16 cols)
    const bool isF = (w < 4);                    // fresh group vs cv group
    const int n0 = n * N_TILE;
    const int q = lane >> 2, tg = lane & 3;

    const unsigned sCV_s = (unsigned)__cvta_generic_to_shared(smem + SM_CV);
    const unsigned sFR_s = (unsigned)__cvta_generic_to_shared(smem + SM_FR);
    const unsigned wt_s  = (unsigned)__cvta_generic_to_shared(Wt);
    const unsigned aOff  = ((lane >> 3) << 7) + ((lane & 7) << 4);
    const unsigned brow  = 16 * wc + 8 * (lane >> 4) + (lane & 7);
    const unsigned bOff  = wt_s + brow * (WT_STRIDE * 2) + (((lane >> 3) & 1) << 4);

    // resident weight slice: Wt[j][k] = W[k][n0+j]
    for (int i = tid; i < N_TILE * 1024; i += THREADS) {
        int j = i >> 10, k = i & 1023;
        float wv = (k < U_) ? Wch[k * U_ + n0 + j] : Wcv[(k - U_) * U_ + n0 + j];
        Wt[j * WT_STRIDE + k] = __float2half_rn(wv);
    }
    if (tid < 64) {
        sWih[tid]       = Wih[n0 + tid];
        sWih[64 + tid]  = Wih[U_ + n0 + tid];
        sWiv[tid]       = Wiv[n0 + tid];
        sWiv[64 + tid]  = Wiv[U_ + n0 + tid];
        sBch[tid]       = bch[n0 + tid];
        sWo0[tid]       = Wout[(n0 + tid) * 2 + 0];
        sWo1[tid]       = Wout[(n0 + tid) * 2 + 1];
    }
    for (int i = tid; i < 4096; i += THREADS) {  // spins for this CTA's 16 rows
        int rl = i & 15, cell = i >> 4;
        sx[cell * 16 + rl] = (unsigned char)x[(16 * m + rl) * 256 + cell];
    }
    __syncthreads();

    int* myflags = g_flags + m * 8;

#pragma unroll 1
    for (int t = 1; t <= T_STEPS; ++t) {
        const int s = t - 1;
        const int r = s >> 4, p = s & 15;
        const int c  = (r & 1) ? (15 - p) : p;
        const int cp = (r & 1) ? (c + 1) : (c - 1);
        const bool has_h = (p > 0), has_v = (r > 0);
        const bool oldcv = has_h && has_v;       // old-cv GEMM active this step
        float* sP = sPart + (t & 1) * 1024;      // parity-selected partial buffer

        if (isF) {
            // ======== FRESH GROUP (warps 0-3, tid 0..127) ========
            // stage 1: only producers 0-3 (their chunks = kk 0..15) + z ring
            if (w == 0 && t > 1) {
                if (lane < 4) {
                    while (ld_acquire(myflags + lane) < t - 1) { }
                }
                if (lane == 8 && t > ZDEPTH) {
                    while (ld_acquire(&g_rflags[m >> 1]) < t - ZDEPTH) { }
                }
            }
            bar_sync(1, 128);                    // (a) first-half deps acquired

            float acc[2][4];
#pragma unroll
            for (int f = 0; f < 2; ++f)
                acc[f][0] = acc[f][1] = acc[f][2] = acc[f][3] = 0.f;

            if (t > 1) {
                const unsigned* fsrc = has_h ? (pslab(r & 1, cp) + (m << 12))
                                             : (pslab((r - 1) & 1, c) + (m << 12));
                // copyA: kk 0-15 (producers 0-3) starts at half-readiness
#pragma unroll
                for (int i = 0; i < 4; ++i)
                    cp_async16(sFR_s + tid * 16 + i * 2048, fsrc + tid * 4 + i * 512);
                cp_commit();

                // stage 2: poll producers 4-7 while copyA is in flight
                if (w == 0 && lane < 4) {
                    while (ld_acquire(myflags + 4 + lane) < t - 1) { }
                }
                bar_sync(1, 128);                // (b) second-half deps acquired
#pragma unroll
                for (int i = 4; i < 8; ++i)
                    cp_async16(sFR_s + tid * 16 + i * 2048, fsrc + tid * 4 + i * 512);
                cp_commit();

                const unsigned bB = has_h ? bOff : bOff + 1024;
                cp_wait<1>();
                bar_sync(1, 128);                // (c) first half staged
                gemm_ldsm_n<16>(sFR_s + aOff, bB, acc);
                cp_wait<0>();
                bar_sync(1, 128);                // (d) second half staged
                gemm_ldsm_n<16>(sFR_s + 8192 + aOff, bB + 512, acc);
            }

            __syncthreads();                     // join: cv partials in sPart[par]

            if (oldcv) {
                const float4* pp = (const float4*)(sP + (wc * 32 + lane) * 8);
                float4 pa = pp[0], pb = pp[1];
                acc[0][0] += pa.x; acc[0][1] += pa.y; acc[0][2] += pa.z; acc[0][3] += pa.w;
                acc[1][0] += pb.x; acc[1][1] += pb.y; acc[1][2] += pb.z; acc[1][3] += pb.w;
            }

            // ---- epilogue
            int sLa = 0, sLb = 0, sUa = 0, sUb = 0;
            if (has_h) {
                sLa = sx[(r * 16 + cp) * 16 + q];
                sLb = sx[(r * 16 + cp) * 16 + q + 8];
            }
            if (has_v) {
                sUa = sx[((r - 1) * 16 + c) * 16 + q];
                sUb = sx[((r - 1) * 16 + c) * 16 + q + 8];
            }

            float z0a = 0.f, z1a = 0.f, z0b = 0.f, z1b = 0.f;
            unsigned* Pout = pslab(r & 1, c) + (m << 12) + ((4 * n + w) << 7) + lane;
#pragma unroll
            for (int f = 0; f < 2; ++f) {
                int u0 = 16 * w + 8 * f + 2 * tg;
                float v0 = acc[f][0] + sBch[u0];
                float v1 = acc[f][1] + sBch[u0 + 1];
                float v2 = acc[f][2] + sBch[u0];
                float v3 = acc[f][3] + sBch[u0 + 1];
                if (has_h) {
                    v0 += sWih[sLa * 64 + u0]; v1 += sWih[sLa * 64 + u0 + 1];
                    v2 += sWih[sLb * 64 + u0]; v3 += sWih[sLb * 64 + u0 + 1];
                }
                if (has_v) {
                    v0 += sWiv[sUa * 64 + u0]; v1 += sWiv[sUa * 64 + u0 + 1];
                    v2 += sWiv[sUb * 64 + u0]; v3 += sWiv[sUb * 64 + u0 + 1];
                }
                v0 = elu1(v0); v1 = elu1(v1); v2 = elu1(v2); v3 = elu1(v3);

                z0a += v0 * sWo0[u0] + v1 * sWo0[u0 + 1];
                z1a += v0 * sWo1[u0] + v1 * sWo1[u0 + 1];
                z0b += v2 * sWo0[u0] + v3 * sWo0[u0 + 1];
                z1b += v2 * sWo1[u0] + v3 * sWo1[u0 + 1];

                Pout[(2 * f) * 32]     = packh2(v0, v1);
                Pout[(2 * f + 1) * 32] = packh2(v2, v3);
            }

            // z quad-reduce + store (reducer consumers)
            z0a += __shfl_xor_sync(0xffffffffu, z0a, 1);
            z0a += __shfl_xor_sync(0xffffffffu, z0a, 2);
            z1a += __shfl_xor_sync(0xffffffffu, z1a, 1);
            z1a += __shfl_xor_sync(0xffffffffu, z1a, 2);
            z0b += __shfl_xor_sync(0xffffffffu, z0b, 1);
            z0b += __shfl_xor_sync(0xffffffffu, z0b, 2);
            z1b += __shfl_xor_sync(0xffffffffu, z1b, 1);
            z1b += __shfl_xor_sync(0xffffffffu, z1b, 2);
            if (tg == 0) {
                float2* zp = g_zpart + (((t & (ZDEPTH - 1)) * NTn + n) * 4 + w) * B_;
                int bA = 16 * m + q;
                zp[bA]     = make_float2(z0a, z1a);
                zp[bA + 8] = make_float2(z0b, z1b);
            }

            bar_sync(1, 128);                    // all fresh stores done
            if (tid == 0) st_release(&g_flags[bx], t);
        } else {
            // ======== CV GROUP (warps 4-7, tid 128..255) ========
            if (oldcv) {
                cp_wait<0>();                    // own prefetch (end of t-1) landed
                bar_sync(2, 128);                // whole cv group staged
                float acc[2][4];
#pragma unroll
                for (int f = 0; f < 2; ++f)
                    acc[f][0] = acc[f][1] = acc[f][2] = acc[f][3] = 0.f;
                gemm_ldsm_n<32>(sCV_s + aOff, bOff + 1024, acc);
                float4* pp = (float4*)(sP + (wc * 32 + lane) * 8);
                pp[0] = make_float4(acc[0][0], acc[0][1], acc[0][2], acc[0][3]);
                pp[1] = make_float4(acc[1][0], acc[1][1], acc[1][2], acc[1][3]);
            }
            bar_sync(2, 128);                    // cv group done reading sCV

            // prefetch next step's old-cv tile into sCV
            if (t < T_STEPS) {
                int r2 = t >> 4, p2 = t & 15;
                if (p2 >= 1 && r2 >= 1) {
                    int c2 = (r2 & 1) ? (15 - p2) : p2;
                    const unsigned* src = pslab((r2 - 1) & 1, c2) + (m << 12);
                    int tl = tid - 128;
#pragma unroll
                    for (int i = 0; i < 8; ++i)
                        cp_async16(sCV_s + tl * 16 + i * 2048, src + tl * 4 + i * 512);
                }
                cp_commit();
            }

            __syncthreads();                     // join (partials visible to fresh)
        }
    }
}

extern "C" void kernel_launch(void* const* d_in, const int* in_sizes, int n_in,
                              void* d_out, int out_size)
{
    (void)in_sizes; (void)n_in; (void)out_size;
    const int*   x    = (const int*)  d_in[0];
    const float* Wih  = (const float*)d_in[1];
    const float* Wiv  = (const float*)d_in[2];
    const float* Wch  = (const float*)d_in[3];
    const float* bch  = (const float*)d_in[4];
    const float* Wcv  = (const float*)d_in[5];
    const float* Wout = (const float*)d_in[6];
    const float* bout = (const float*)d_in[7];
    float* out = (float*)d_out;

    cudaFuncSetAttribute(rnn2d_main_kernel,
                         cudaFuncAttributeMaxDynamicSharedMemorySize, SM_TOTAL);

    rnn2d_init_kernel<<<1, 128>>>();
    rnn2d_main_kernel<<<NCOMP + NRED, THREADS, SM_TOTAL>>>(
        x, Wih, Wiv, Wch, bch, Wcv, Wout, bout, out);
}